// round 4
// baseline (speedup 1.0000x reference)
#include <cuda_runtime.h>

// Fully fused kernel: every block redundantly computes the batch-independent
// constants from the weights (cheap, parallel, smem-staged), then streams its
// slice of x:   out_b = S1*cross(M1 x_b, M2 x_b) + S2*x_b + C

__device__ __forceinline__ void apply3(const float* __restrict__ c,
                                       float x0, float x1, float x2,
                                       float& o0, float& o1, float& o2)
{
    float p0 = c[0]*x0 + c[1]*x1 + c[2]*x2;
    float p1 = c[3]*x0 + c[4]*x1 + c[5]*x2;
    float p2 = c[6]*x0 + c[7]*x1 + c[8]*x2;
    float q0 = c[9]*x0  + c[10]*x1 + c[11]*x2;
    float q1 = c[12]*x0 + c[13]*x1 + c[14]*x2;
    float q2 = c[15]*x0 + c[16]*x1 + c[17]*x2;
    float r0 = p1*q2 - p2*q1;
    float r1 = p2*q0 - p0*q2;
    float r2 = p0*q1 - p1*q0;
    o0 = c[18]*r0 + c[19]*x0 + c[20];
    o1 = c[18]*r1 + c[19]*x1 + c[21];
    o2 = c[18]*r2 + c[19]*x2 + c[22];
}

__global__ __launch_bounds__(256)
void fused_kernel(const float4* __restrict__ xin, float4* __restrict__ xout,
                  const float* __restrict__ xin_s, float* __restrict__ xout_s,
                  const float* __restrict__ t_, const float* __restrict__ R,
                  const float* __restrict__ m,
                  const float* __restrict__ Wl1, const float* __restrict__ Wd1,
                  const float* __restrict__ Wl2, const float* __restrict__ Wd2,
                  const float* __restrict__ Wl3, const float* __restrict__ Wd3,
                  const float* __restrict__ Wl4, const float* __restrict__ Wd4,
                  const float* __restrict__ Wb1_lin, const float* __restrict__ Wb1_d1,
                  const float* __restrict__ Wb1_d2, const float* __restrict__ Wb2_lin,
                  const float* __restrict__ Wb2_d1, const float* __restrict__ Wb2_d2,
                  const float* __restrict__ Wout,
                  int n8, int B)
{
    __shared__ float sR[9], sm[60];
    __shared__ float sWl[4][60], sWd[4][9];
    __shared__ float sLin1[20], sLin2[20], sWout[20];
    __shared__ float sBd[4][400];
    __shared__ float smm[60];          // [f*3+k]
    __shared__ float su[3];
    __shared__ float sz[4][9];         // [i][c*3+k]
    __shared__ float sy[4][9];
    __shared__ float sM[4][9];
    __shared__ float srow[4][20];      // a1,a2,b1,b2 per f
    __shared__ float sc[23];

    const int tid = threadIdx.x;

    // ---- cooperative weight staging ----
    {
        const float* Wls[4] = {Wl1, Wl2, Wl3, Wl4};
        const float* Wds[4] = {Wd1, Wd2, Wd3, Wd4};
        const float* Bds[4] = {Wb1_d1, Wb1_d2, Wb2_d1, Wb2_d2};
        if (tid < 9)  sR[tid] = R[tid];
        if (tid < 60) sm[tid] = m[tid];
        #pragma unroll
        for (int i = 0; i < 4; i++) {
            if (tid < 60) sWl[i][tid] = Wls[i][tid];
            if (tid < 9)  sWd[i][tid] = Wds[i][tid];
        }
        if (tid < 20) { sLin1[tid] = Wb1_lin[tid]; sLin2[tid] = Wb2_lin[tid]; sWout[tid] = Wout[tid]; }
        #pragma unroll
        for (int i = 0; i < 4; i++)
            for (int j = tid; j < 400; j += 256) sBd[i][j] = Bds[i][j];
    }
    __syncthreads();

    // ---- stage 1: mm[f][k] = (R@m)[k,f]; u = R @ 10*[sin,cos,sin](t) ----
    if (tid < 60) {
        int f = tid / 3, k = tid % 3;
        smm[tid] = sR[k*3+0]*sm[f] + sR[k*3+1]*sm[20+f] + sR[k*3+2]*sm[40+f];
    } else if (tid < 63) {
        int k = tid - 60;
        float t = t_[0];
        float st = 10.f * sinf(t), ct = 10.f * cosf(t);
        su[k] = sR[k*3+0]*st + sR[k*3+1]*ct + sR[k*3+2]*st;
    }
    __syncthreads();

    // ---- stage 2: z[i][o][k] (36 thr) and row dots (80 thr) ----
    if (tid < 36) {
        int i = tid / 9, o = (tid % 9) / 3, k = tid % 3;
        float acc = 0.f;
        #pragma unroll
        for (int f = 0; f < 20; f++) acc += sWl[i][o*20+f] * smm[f*3+k];
        sz[i][o*3+k] = acc;
    } else if (tid >= 64 && tid < 144) {
        int j = tid - 64, mat = j / 20, f = j % 20;
        const float* lin = (mat < 2) ? sLin1 : sLin2;
        float acc = 0.f;
        #pragma unroll
        for (int g = 0; g < 20; g++) acc += sBd[mat][f*20+g] * lin[g];
        srow[mat][f] = acc;
    }
    __syncthreads();

    // ---- stage 3: Killing ReLU per (i,o) -> y ----
    if (tid < 12) {
        int i = tid / 3, o = tid % 3;
        float zz[3], d[3];
        #pragma unroll
        for (int k = 0; k < 3; k++) {
            zz[k] = sz[i][o*3+k];
            d[k]  = sWd[i][o*3+0]*sz[i][0*3+k] + sWd[i][o*3+1]*sz[i][1*3+k] + sWd[i][o*3+2]*sz[i][2*3+k];
        }
        float kxd = -2.f * (zz[0]*d[0] + zz[1]*d[1] + zz[2]*d[2]);
        float kdd = -2.f * (d[0]*d[0] + d[1]*d[1] + d[2]*d[2]);
        float denom = fminf(kdd, -1e-12f);
        float r = kxd / denom;
        #pragma unroll
        for (int k = 0; k < 3; k++)
            sy[i][o*3+k] = (kxd < 0.f) ? zz[k] : (zz[k] - r * d[k]);
    }
    __syncthreads();

    // ---- stage 4: M_i[k][kk] = sum_o y[o][k] y[o][kk] ----
    if (tid < 36) {
        int i = tid / 9, k = (tid % 9) / 3, kk = tid % 3;
        sM[i][k*3+kk] = sy[i][0*3+k]*sy[i][0*3+kk] + sy[i][1*3+k]*sy[i][1*3+kk] + sy[i][2*3+k]*sy[i][2*3+kk];
    }
    __syncthreads();

    // ---- stage 5: final scalars + constant vector ----
    if (tid == 0) {
        float S1 = 0.f, S2 = 0.f, T1 = 0.f, T2 = 0.f;
        #pragma unroll
        for (int f = 0; f < 20; f++) {
            S1 += sWout[f] * srow[0][f] * srow[1][f];
            S2 += sWout[f] * sLin1[f];
            T1 += sWout[f] * srow[2][f] * srow[3][f];
            T2 += sWout[f] * sLin2[f];
        }
        float p[3], q[3];
        #pragma unroll
        for (int k = 0; k < 3; k++) {
            p[k] = sM[2][k*3+0]*su[0] + sM[2][k*3+1]*su[1] + sM[2][k*3+2]*su[2];
            q[k] = sM[3][k*3+0]*su[0] + sM[3][k*3+1]*su[1] + sM[3][k*3+2]*su[2];
        }
        float cr0 = p[1]*q[2] - p[2]*q[1];
        float cr1 = p[2]*q[0] - p[0]*q[2];
        float cr2 = p[0]*q[1] - p[1]*q[0];
        #pragma unroll
        for (int i = 0; i < 9; i++) { sc[i] = sM[0][i]; sc[9+i] = sM[1][i]; }
        sc[18] = S1;
        sc[19] = S2;
        sc[20] = T1*cr0 + T2*su[0];
        sc[21] = T1*cr1 + T2*su[1];
        sc[22] = T1*cr2 + T2*su[2];
    }
    __syncthreads();

    float c[23];
    #pragma unroll
    for (int i = 0; i < 23; i++) c[i] = sc[i];

    // ---- streaming phase: 8 elements (6 float4) per thread ----
    int g = blockIdx.x * 256 + tid;
    if (g < n8) {
        float4 v[6];
        #pragma unroll
        for (int i = 0; i < 6; i++) v[i] = xin[6*g + i];
        float xs[24], os[24];
        #pragma unroll
        for (int i = 0; i < 6; i++) {
            xs[4*i+0] = v[i].x; xs[4*i+1] = v[i].y; xs[4*i+2] = v[i].z; xs[4*i+3] = v[i].w;
        }
        #pragma unroll
        for (int e = 0; e < 8; e++)
            apply3(c, xs[3*e], xs[3*e+1], xs[3*e+2], os[3*e], os[3*e+1], os[3*e+2]);
        #pragma unroll
        for (int i = 0; i < 6; i++)
            xout[6*g + i] = make_float4(os[4*i+0], os[4*i+1], os[4*i+2], os[4*i+3]);
    } else if (g == n8) {
        for (int e = 8*n8; e < B; e++) {
            float o0, o1, o2;
            apply3(c, xin_s[3*e], xin_s[3*e+1], xin_s[3*e+2], o0, o1, o2);
            xout_s[3*e] = o0; xout_s[3*e+1] = o1; xout_s[3*e+2] = o2;
        }
    }
}

extern "C" void kernel_launch(void* const* d_in, const int* in_sizes, int n_in,
                              void* d_out, int out_size)
{
    const float* t       = (const float*)d_in[0];
    const float* x       = (const float*)d_in[1];
    const float* R       = (const float*)d_in[2];
    const float* m       = (const float*)d_in[3];
    const float* Wl1     = (const float*)d_in[4];
    const float* Wd1     = (const float*)d_in[5];
    const float* Wl2     = (const float*)d_in[6];
    const float* Wd2     = (const float*)d_in[7];
    const float* Wl3     = (const float*)d_in[8];
    const float* Wd3     = (const float*)d_in[9];
    const float* Wl4     = (const float*)d_in[10];
    const float* Wd4     = (const float*)d_in[11];
    const float* Wb1_lin = (const float*)d_in[12];
    const float* Wb1_d1  = (const float*)d_in[13];
    const float* Wb1_d2  = (const float*)d_in[14];
    const float* Wb2_lin = (const float*)d_in[15];
    const float* Wb2_d1  = (const float*)d_in[16];
    const float* Wb2_d2  = (const float*)d_in[17];
    const float* Wout    = (const float*)d_in[18];

    int B = in_sizes[1] / 3;
    int n8 = B / 8;
    int rem = B - 8 * n8;
    int total_threads = n8 + (rem ? 1 : 0);
    int blocks = (total_threads + 255) / 256;
    if (blocks < 1) blocks = 1;

    fused_kernel<<<blocks, 256>>>((const float4*)x, (float4*)d_out, x, (float*)d_out,
                                  t, R, m, Wl1, Wd1, Wl2, Wd2, Wl3, Wd3, Wl4, Wd4,
                                  Wb1_lin, Wb1_d1, Wb1_d2, Wb2_lin, Wb2_d1, Wb2_d2,
                                  Wout, n8, B);
}